// round 3
// baseline (speedup 1.0000x reference)
#include <cuda_runtime.h>

#define BATCH 16
#define HW    16384
#define C     64
#define K1_CHUNKS 64

// Deterministic scratch (no atomics, fully overwritten every launch)
__device__ float g_partial[BATCH * K1_CHUNKS * C * C];  // 16 MB
__device__ float g_attn[BATCH * C * C];

__device__ __forceinline__ void ffma2(unsigned long long &d,
                                      unsigned long long a,
                                      unsigned long long b) {
    asm("fma.rn.f32x2 %0, %1, %2, %0;" : "+l"(d) : "l"(a), "l"(b));
}

// duplicate a float into both halves of an f32x2 register pair (1 MOV, alu pipe)
__device__ __forceinline__ unsigned long long dup2(float v) {
    unsigned long long d;
    asm("mov.b64 %0, {%1, %1};" : "=l"(d) : "f"(v));
    return d;
}

// ---------------------------------------------------------------------------
// Kernel 1: partial scores.  S_partial[b][chunk][q][k] = sum_rows Q[r][q]*K[r][k]
// 64 threads: tx = k-group (8 k = 4 pairs), ty = q-group (8 q, reg-duplicated).
// Thread tile 8q x 8k -> 32 FFMA2 per row vs 4 LDS.128 + 8 MOV.
// ---------------------------------------------------------------------------
__global__ __launch_bounds__(64) void k1_scores(const float* __restrict__ Q,
                                                const float* __restrict__ K) {
    __shared__ __align__(16) float Qs[32][68];
    __shared__ __align__(16) float Ks[32][68];

    int b     = blockIdx.x >> 6;
    int chunk = blockIdx.x & 63;
    int t  = threadIdx.x;
    int tx = t & 7;    // k = 8*tx .. 8*tx+7
    int ty = t >> 3;   // q = 8*ty .. 8*ty+7

    unsigned long long c2[8][4];
#pragma unroll
    for (int i = 0; i < 8; ++i)
#pragma unroll
        for (int j = 0; j < 4; ++j) c2[i][j] = 0ull;

    const float* Qb = Q + ((size_t)b * HW + chunk * 256) * C;
    const float* Kb = K + ((size_t)b * HW + chunk * 256) * C;

    for (int tile = 0; tile < 8; ++tile) {
        // stage 32 rows of Q and K (coalesced float4)
#pragma unroll
        for (int it = 0; it < 8; ++it) {
            int idx = t + it * 64;           // 0..511
            int r = idx >> 4, c4 = idx & 15;
            const float* src = Qb + (size_t)(tile * 32 + r) * C + c4 * 4;
            *(float4*)&Qs[r][c4 * 4] = *(const float4*)src;
            src = Kb + (size_t)(tile * 32 + r) * C + c4 * 4;
            *(float4*)&Ks[r][c4 * 4] = *(const float4*)src;
        }
        __syncthreads();

#pragma unroll 4
        for (int r = 0; r < 32; ++r) {
            float4 qa = *(const float4*)&Qs[r][ty * 8];
            float4 qb = *(const float4*)&Qs[r][ty * 8 + 4];
            ulonglong2 ka = *(const ulonglong2*)&Ks[r][tx * 8];
            ulonglong2 kb = *(const ulonglong2*)&Ks[r][tx * 8 + 4];
            unsigned long long kk[4] = {ka.x, ka.y, kb.x, kb.y};
            unsigned long long qd[8] = {dup2(qa.x), dup2(qa.y), dup2(qa.z), dup2(qa.w),
                                        dup2(qb.x), dup2(qb.y), dup2(qb.z), dup2(qb.w)};
#pragma unroll
            for (int i = 0; i < 8; ++i)
#pragma unroll
                for (int j = 0; j < 4; ++j) ffma2(c2[i][j], qd[i], kk[j]);
        }
        __syncthreads();
    }

    float* pb = g_partial + (size_t)(b * K1_CHUNKS + chunk) * (C * C);
#pragma unroll
    for (int i = 0; i < 8; ++i) {
        int q = ty * 8 + i;
        *(ulonglong2*)(pb + q * C + tx * 8)     = make_ulonglong2(c2[i][0], c2[i][1]);
        *(ulonglong2*)(pb + q * C + tx * 8 + 4) = make_ulonglong2(c2[i][2], c2[i][3]);
    }
}

// ---------------------------------------------------------------------------
// Kernel 2: reduce 64 chunk partials + softmax over k (unchanged, ~8us)
// ---------------------------------------------------------------------------
__global__ __launch_bounds__(256) void k2_softmax() {
    __shared__ float S[256];
    int b  = blockIdx.x >> 4;
    int qg = blockIdx.x & 15;
    int t  = threadIdx.x;
    int q  = qg * 4 + (t >> 6);
    int k  = t & 63;

    const float* p = g_partial + (size_t)b * K1_CHUNKS * (C * C) + q * C + k;
    float acc = 0.f;
#pragma unroll 8
    for (int ch = 0; ch < K1_CHUNKS; ++ch) acc += p[(size_t)ch * (C * C)];
    S[t] = acc;
    __syncthreads();

    int w = t >> 5, lane = t & 31;
    if (w < 4) {
        float e0 = S[w * 64 + lane];
        float e1 = S[w * 64 + 32 + lane];
        float m = fmaxf(e0, e1);
#pragma unroll
        for (int o = 16; o > 0; o >>= 1) m = fmaxf(m, __shfl_xor_sync(~0u, m, o));
        float x0 = expf(e0 - m), x1 = expf(e1 - m);
        float s = x0 + x1;
#pragma unroll
        for (int o = 16; o > 0; o >>= 1) s += __shfl_xor_sync(~0u, s, o);
        float inv = 1.f / s;
        float* a = g_attn + (size_t)b * (C * C) + (qg * 4 + w) * C;
        a[lane]      = x0 * inv;
        a[lane + 32] = x1 * inv;
    }
}

// ---------------------------------------------------------------------------
// Kernel 3: out[b][row][q] = sum_k attn[b][q][k] * V[b][row][k]
// 64 threads: tx = q-group (8 q = 4 pairs from At), ty = row-group (8 rows).
// V read as float4 along k (4 k per step, conflict-free), reg-duplicated.
// ---------------------------------------------------------------------------
__global__ __launch_bounds__(64) void k3_out(const float* __restrict__ V,
                                             float* __restrict__ O) {
    __shared__ __align__(16) float At[64][68];   // At[k][q] = attn[q][k]
    __shared__ __align__(16) float Vs[64][68];   // Vs[row][k]

    int b  = blockIdx.x >> 6;
    int rc = blockIdx.x & 63;
    int t  = threadIdx.x;
    int tx = t & 7;    // q = 8*tx .. 8*tx+7
    int ty = t >> 3;   // rows = 8*ty .. 8*ty+7 within 64-row stage

    const float* ab = g_attn + (size_t)b * (C * C);
#pragma unroll
    for (int it = 0; it < 64; ++it) {
        int idx = t + it * 64;       // 0..4095
        int q = idx >> 6, k = idx & 63;
        At[k][q] = ab[idx];
    }

    const float* Vb = V + ((size_t)b * HW + rc * 256) * C;
    float*       Ob = O + ((size_t)b * HW + rc * 256) * C;

    for (int st = 0; st < 4; ++st) {
        __syncthreads();   // At ready (st=0) / Vs reuse safe (st>0)
#pragma unroll
        for (int it = 0; it < 16; ++it) {
            int idx = t + it * 64;   // 0..1023 : 64 rows x 16 float4
            int r = idx >> 4, c4 = idx & 15;
            *(float4*)&Vs[r][c4 * 4] =
                *(const float4*)(Vb + (size_t)(st * 64 + r) * C + c4 * 4);
        }
        __syncthreads();

        unsigned long long c2[8][4];  // [row][q-pair]
#pragma unroll
        for (int i = 0; i < 8; ++i)
#pragma unroll
            for (int j = 0; j < 4; ++j) c2[i][j] = 0ull;

#pragma unroll 2
        for (int k4 = 0; k4 < 16; ++k4) {
            int k0 = k4 * 4;
            float4 vv[8];
#pragma unroll
            for (int i = 0; i < 8; ++i)
                vv[i] = *(const float4*)&Vs[ty * 8 + i][k0];
#pragma unroll
            for (int kk = 0; kk < 4; ++kk) {
                int k = k0 + kk;
                ulonglong2 a0 = *(const ulonglong2*)&At[k][tx * 8];
                ulonglong2 a1 = *(const ulonglong2*)&At[k][tx * 8 + 4];
                unsigned long long aa[4] = {a0.x, a0.y, a1.x, a1.y};
#pragma unroll
                for (int i = 0; i < 8; ++i) {
                    float v = (kk == 0) ? vv[i].x : (kk == 1) ? vv[i].y
                            : (kk == 2) ? vv[i].z : vv[i].w;
                    unsigned long long vd = dup2(v);
                    ffma2(c2[i][0], vd, aa[0]);
                    ffma2(c2[i][1], vd, aa[1]);
                    ffma2(c2[i][2], vd, aa[2]);
                    ffma2(c2[i][3], vd, aa[3]);
                }
            }
        }

#pragma unroll
        for (int i = 0; i < 8; ++i) {
            int row = st * 64 + ty * 8 + i;
            *(ulonglong2*)(Ob + (size_t)row * C + tx * 8) =
                make_ulonglong2(c2[i][0], c2[i][1]);
            *(ulonglong2*)(Ob + (size_t)row * C + tx * 8 + 4) =
                make_ulonglong2(c2[i][2], c2[i][3]);
        }
    }
}

// ---------------------------------------------------------------------------
extern "C" void kernel_launch(void* const* d_in, const int* in_sizes, int n_in,
                              void* d_out, int out_size) {
    const float* q = (const float*)d_in[0];
    const float* k = (const float*)d_in[1];
    const float* v = (const float*)d_in[2];
    float* out = (float*)d_out;

    k1_scores<<<BATCH * K1_CHUNKS, 64>>>(q, k);
    k2_softmax<<<BATCH * 16, 256>>>();
    k3_out<<<BATCH * K1_CHUNKS, 64>>>(v, out);
}

// round 5
// speedup vs baseline: 1.5113x; 1.5113x over previous
#include <cuda_runtime.h>
#include <cstdint>

#define BATCH 16
#define HW    16384
#define C     64
#define CHUNKS 32            // k1/k3: 512 rows per CTA, 8 stages of 64

__device__ float g_partial[BATCH * CHUNKS * C * C];   // 8 MB scratch
__device__ float g_attn[BATCH * C * C];

// ---------------------------------------------------------------------------
// helpers
// ---------------------------------------------------------------------------
__device__ __forceinline__ uint32_t smem_u32(const void* p) {
    uint32_t a;
    asm("{ .reg .u64 t; cvta.to.shared.u64 t, %1; cvt.u32.u64 %0, t; }"
        : "=r"(a) : "l"(p));
    return a;
}
__device__ __forceinline__ uint32_t sw128(uint32_t o) {
    return o ^ ((o >> 3) & 0x70);
}
// pack hi-16 bits of two fp32 -> bf16x2 (lo = first)
__device__ __forceinline__ uint32_t prmt_hi(float a, float b) {
    uint32_t d;
    asm("prmt.b32 %0, %1, %2, 0x7632;"
        : "=r"(d) : "r"(__float_as_uint(a)), "r"(__float_as_uint(b)));
    return d;
}
__device__ __forceinline__ float trunc_hi(float x) {
    return __uint_as_float(__float_as_uint(x) & 0xFFFF0000u);
}

#define LDSM4T(r, a)                                                          \
    asm volatile("ldmatrix.sync.aligned.m8n8.x4.trans.shared.b16 "            \
                 "{%0,%1,%2,%3}, [%4];"                                       \
                 : "=r"((r)[0]), "=r"((r)[1]), "=r"((r)[2]), "=r"((r)[3])     \
                 : "r"(a))
#define LDSM4(r, a)                                                           \
    asm volatile("ldmatrix.sync.aligned.m8n8.x4.shared.b16 "                  \
                 "{%0,%1,%2,%3}, [%4];"                                       \
                 : "=r"((r)[0]), "=r"((r)[1]), "=r"((r)[2]), "=r"((r)[3])     \
                 : "r"(a))
#define MMA(d, a, b0, b1)                                                     \
    asm volatile("mma.sync.aligned.m16n8k16.row.col.f32.bf16.bf16.f32 "       \
                 "{%0,%1,%2,%3}, {%4,%5,%6,%7}, {%8,%9}, {%0,%1,%2,%3};"      \
                 : "+f"((d)[0]), "+f"((d)[1]), "+f"((d)[2]), "+f"((d)[3])     \
                 : "r"((a)[0]), "r"((a)[1]), "r"((a)[2]), "r"((a)[3]),        \
                   "r"(b0), "r"(b1))

// tile: 64 rows x 64 bf16 cols, 128B row stride, SW128 swizzle, 8KB
#define TILE 8192

// ---------------------------------------------------------------------------
// Kernel 1: partial scores. S[b][q][k] = sum_r Q[b][r][q]*K[b][r][k]
// A = Q^T (ldmatrix.trans), B = K (ldmatrix.trans). 3-level exact bf16 split,
// 6 products accumulated into the same fp32 C fragments.
// ---------------------------------------------------------------------------
__global__ void __launch_bounds__(128, 4)
k1_scores(const float* __restrict__ Q, const float* __restrict__ K) {
    __shared__ __align__(1024) uint8_t sm[6 * TILE];   // Q1 Q2 Q3 K1 K2 K3
    uint32_t sb = smem_u32(sm);

    int t = threadIdx.x, lane = t & 31, w = t >> 5;
    int b = blockIdx.x >> 5;
    int chunk = blockIdx.x & 31;
    int qb = w * 16;

    const float* Qb = Q + ((size_t)b * HW + chunk * 512) * C;
    const float* Kb = K + ((size_t)b * HW + chunk * 512) * C;

    float d[8][4];
#pragma unroll
    for (int i = 0; i < 8; ++i)
#pragma unroll
        for (int j = 0; j < 4; ++j) d[i][j] = 0.f;

    const int li = lane & 7, mi = lane >> 3;
    const int rA = ((mi & 2) << 2) + li;          // A: row+8 on mi bit1
    const int cA = qb + ((mi & 1) << 3);          //    col+8 on mi bit0
    const int rB = ((mi & 1) << 3) + li;          // B: row+8 on mi bit0
    const int cBo = (mi & 2) << 2;                //    col+8 on mi bit1

    for (int s = 0; s < 8; ++s) {
        __syncthreads();   // prev-stage ldmatrix reads complete
        // load + exact 3-level split, both Q and K
#pragma unroll
        for (int it = 0; it < 8; ++it) {
            int idx = t + it * 128;               // 0..1023
            int r = idx >> 4, c4 = idx & 15;
            uint32_t off = sw128((uint32_t)(r * 128 + c4 * 8));
            {
                float4 x = *(const float4*)(Qb + (size_t)(s * 64 + r) * C + c4 * 4);
                float r1x = x.x - trunc_hi(x.x), r1y = x.y - trunc_hi(x.y);
                float r1z = x.z - trunc_hi(x.z), r1w = x.w - trunc_hi(x.w);
                float r2x = r1x - trunc_hi(r1x), r2y = r1y - trunc_hi(r1y);
                float r2z = r1z - trunc_hi(r1z), r2w = r1w - trunc_hi(r1w);
                *(uint2*)(sm + 0 * TILE + off) =
                    make_uint2(prmt_hi(x.x, x.y), prmt_hi(x.z, x.w));
                *(uint2*)(sm + 1 * TILE + off) =
                    make_uint2(prmt_hi(r1x, r1y), prmt_hi(r1z, r1w));
                *(uint2*)(sm + 2 * TILE + off) =
                    make_uint2(prmt_hi(r2x, r2y), prmt_hi(r2z, r2w));
            }
            {
                float4 x = *(const float4*)(Kb + (size_t)(s * 64 + r) * C + c4 * 4);
                float r1x = x.x - trunc_hi(x.x), r1y = x.y - trunc_hi(x.y);
                float r1z = x.z - trunc_hi(x.z), r1w = x.w - trunc_hi(x.w);
                float r2x = r1x - trunc_hi(r1x), r2y = r1y - trunc_hi(r1y);
                float r2z = r1z - trunc_hi(r1z), r2w = r1w - trunc_hi(r1w);
                *(uint2*)(sm + 3 * TILE + off) =
                    make_uint2(prmt_hi(x.x, x.y), prmt_hi(x.z, x.w));
                *(uint2*)(sm + 4 * TILE + off) =
                    make_uint2(prmt_hi(r1x, r1y), prmt_hi(r1z, r1w));
                *(uint2*)(sm + 5 * TILE + off) =
                    make_uint2(prmt_hi(r2x, r2y), prmt_hi(r2z, r2w));
            }
        }
        __syncthreads();

#pragma unroll
        for (int kst = 0; kst < 4; ++kst) {
            int r0 = kst * 16;
            uint32_t A1[4], A2[4], A3[4];
            uint32_t aoff = sw128((uint32_t)((r0 + rA) * 128 + cA * 2));
            LDSM4T(A1, sb + 0 * TILE + aoff);
            LDSM4T(A2, sb + 1 * TILE + aoff);
            LDSM4T(A3, sb + 2 * TILE + aoff);
#pragma unroll
            for (int np = 0; np < 4; ++np) {
                uint32_t B1[4], B2[4], B3[4];
                uint32_t boff =
                    sw128((uint32_t)((r0 + rB) * 128 + (np * 16 + cBo) * 2));
                LDSM4T(B1, sb + 3 * TILE + boff);
                LDSM4T(B2, sb + 4 * TILE + boff);
                LDSM4T(B3, sb + 5 * TILE + boff);
                float* d0 = d[2 * np];
                float* d1 = d[2 * np + 1];
                MMA(d0, A1, B1[0], B1[1]); MMA(d1, A1, B1[2], B1[3]);
                MMA(d0, A1, B2[0], B2[1]); MMA(d1, A1, B2[2], B2[3]);
                MMA(d0, A2, B1[0], B1[1]); MMA(d1, A2, B1[2], B1[3]);
                MMA(d0, A2, B2[0], B2[1]); MMA(d1, A2, B2[2], B2[3]);
                MMA(d0, A1, B3[0], B3[1]); MMA(d1, A1, B3[2], B3[3]);
                MMA(d0, A3, B1[0], B1[1]); MMA(d1, A3, B1[2], B1[3]);
            }
        }
    }

    // epilogue: C fragments -> g_partial[b][chunk][q][k]
    float* pb = g_partial + ((size_t)b * CHUNKS + chunk) * (C * C);
    int mrow = qb + (lane >> 2);
    int mcol = 2 * (lane & 3);
#pragma unroll
    for (int nt = 0; nt < 8; ++nt) {
        *(float2*)(pb + mrow * C + nt * 8 + mcol) = make_float2(d[nt][0], d[nt][1]);
        *(float2*)(pb + (mrow + 8) * C + nt * 8 + mcol) = make_float2(d[nt][2], d[nt][3]);
    }
}

// ---------------------------------------------------------------------------
// Kernel 2: reduce 32 chunk partials + softmax over k.
// ---------------------------------------------------------------------------
__global__ __launch_bounds__(256) void k2_softmax() {
    __shared__ float S[256];
    int b = blockIdx.x >> 4;
    int qg = blockIdx.x & 15;
    int t = threadIdx.x;
    int q = qg * 4 + (t >> 6);
    int k = t & 63;

    const float* p = g_partial + (size_t)b * CHUNKS * (C * C) + q * C + k;
    float acc = 0.f;
#pragma unroll 8
    for (int ch = 0; ch < CHUNKS; ++ch) acc += p[(size_t)ch * (C * C)];
    S[t] = acc;
    __syncthreads();

    int w = t >> 5, lane = t & 31;
    if (w < 4) {
        float e0 = S[w * 64 + lane];
        float e1 = S[w * 64 + 32 + lane];
        float m = fmaxf(e0, e1);
#pragma unroll
        for (int o = 16; o > 0; o >>= 1) m = fmaxf(m, __shfl_xor_sync(~0u, m, o));
        float x0 = expf(e0 - m), x1 = expf(e1 - m);
        float s = x0 + x1;
#pragma unroll
        for (int o = 16; o > 0; o >>= 1) s += __shfl_xor_sync(~0u, s, o);
        float inv = 1.f / s;
        float* a = g_attn + (size_t)b * (C * C) + (qg * 4 + w) * C;
        a[lane] = x0 * inv;
        a[lane + 32] = x1 * inv;
    }
}

// ---------------------------------------------------------------------------
// Kernel 3: out[b][r][q] = sum_k attn[b][q][k] * V[b][r][k]
// A = V (non-trans ldmatrix), B = attn^T (trans ldmatrix, staged once).
// 2-level split, 3 products.
// ---------------------------------------------------------------------------
__global__ void __launch_bounds__(128, 4)
k3_out(const float* __restrict__ V, float* __restrict__ O) {
    __shared__ __align__(1024) uint8_t sm[4 * TILE];   // Vh Vl Bh Bl
    uint32_t sb = smem_u32(sm);

    int t = threadIdx.x, lane = t & 31, w = t >> 5;
    int b = blockIdx.x >> 5;
    int rg = blockIdx.x & 31;
    size_t row0 = (size_t)b * HW + rg * 512;

    // stage attn^T once: sB[k][q], 2 levels
    const float* ab = g_attn + (size_t)b * (C * C);
#pragma unroll
    for (int it = 0; it < 8; ++it) {
        int idx = t + it * 128;
        int q = idx >> 4, c4 = idx & 15;
        float4 x = *(const float4*)(ab + q * 64 + c4 * 4);
        float xs[4] = {x.x, x.y, x.z, x.w};
#pragma unroll
        for (int j = 0; j < 4; ++j) {
            int k = c4 * 4 + j;
            uint32_t off = sw128((uint32_t)(k * 128 + q * 2));
            float h = trunc_hi(xs[j]);
            *(uint16_t*)(sm + 2 * TILE + off) =
                (uint16_t)(__float_as_uint(xs[j]) >> 16);
            *(uint16_t*)(sm + 3 * TILE + off) =
                (uint16_t)(__float_as_uint(xs[j] - h) >> 16);
        }
    }

    const int li = lane & 7, mi = lane >> 3;
    const int rVA = w * 16 + ((mi & 1) << 3) + li;   // A non-trans: row+8 bit0
    const int cVAo = (mi & 2) << 2;                  //              col+8 bit1
    const int rB = ((mi & 1) << 3) + li;
    const int cBo = (mi & 2) << 2;
    int mrow = w * 16 + (lane >> 2);
    int mcol = 2 * (lane & 3);

    for (int s = 0; s < 8; ++s) {
        __syncthreads();
        // stage V 64 rows, 2-level split
#pragma unroll
        for (int it = 0; it < 8; ++it) {
            int idx = t + it * 128;
            int r = idx >> 4, c4 = idx & 15;
            float4 x = *(const float4*)(V + (row0 + s * 64 + r) * C + c4 * 4);
            float r1x = x.x - trunc_hi(x.x), r1y = x.y - trunc_hi(x.y);
            float r1z = x.z - trunc_hi(x.z), r1w = x.w - trunc_hi(x.w);
            uint32_t off = sw128((uint32_t)(r * 128 + c4 * 8));
            *(uint2*)(sm + 0 * TILE + off) =
                make_uint2(prmt_hi(x.x, x.y), prmt_hi(x.z, x.w));
            *(uint2*)(sm + 1 * TILE + off) =
                make_uint2(prmt_hi(r1x, r1y), prmt_hi(r1z, r1w));
        }
        __syncthreads();

        float d[8][4];
#pragma unroll
        for (int i = 0; i < 8; ++i)
#pragma unroll
            for (int j = 0; j < 4; ++j) d[i][j] = 0.f;

#pragma unroll
        for (int kst = 0; kst < 4; ++kst) {
            int k0 = kst * 16;
            uint32_t Ah[4], Al[4];
            uint32_t aoff = sw128((uint32_t)(rVA * 128 + (k0 + cVAo) * 2));
            LDSM4(Ah, sb + 0 * TILE + aoff);
            LDSM4(Al, sb + 1 * TILE + aoff);
#pragma unroll
            for (int np = 0; np < 4; ++np) {
                uint32_t Bh[4], Bl[4];
                uint32_t boff =
                    sw128((uint32_t)((k0 + rB) * 128 + (np * 16 + cBo) * 2));
                LDSM4T(Bh, sb + 2 * TILE + boff);
                LDSM4T(Bl, sb + 3 * TILE + boff);
                float* d0 = d[2 * np];
                float* d1 = d[2 * np + 1];
                MMA(d0, Ah, Bh[0], Bh[1]); MMA(d1, Ah, Bh[2], Bh[3]);
                MMA(d0, Ah, Bl[0], Bl[1]); MMA(d1, Ah, Bl[2], Bl[3]);
                MMA(d0, Al, Bh[0], Bh[1]); MMA(d1, Al, Bh[2], Bh[3]);
            }
        }

        float* Ob = O + (row0 + s * 64) * C;
#pragma unroll
        for (int nt = 0; nt < 8; ++nt) {
            *(float2*)(Ob + (size_t)mrow * C + nt * 8 + mcol) =
                make_float2(d[nt][0], d[nt][1]);
            *(float2*)(Ob + (size_t)(mrow + 8) * C + nt * 8 + mcol) =
                make_float2(d[nt][2], d[nt][3]);
        }
    }
}

// ---------------------------------------------------------------------------
extern "C" void kernel_launch(void* const* d_in, const int* in_sizes, int n_in,
                              void* d_out, int out_size) {
    const float* q = (const float*)d_in[0];
    const float* k = (const float*)d_in[1];
    const float* v = (const float*)d_in[2];
    float* out = (float*)d_out;

    k1_scores<<<BATCH * CHUNKS, 128>>>(q, k);
    k2_softmax<<<BATCH * 16, 256>>>();
    k3_out<<<BATCH * CHUNKS, 128>>>(v, out);
}